// round 16
// baseline (speedup 1.0000x reference)
#include <cuda_runtime.h>
#include <cuda_fp16.h>
#include <cstdint>

// TALayer = 9-tap conv, tap offsets d_j = 16*(j/3)+(j%3)-17.
// GEMM: D[o,t] = sum_k W[o,k]*X[k,t], k=(j,c), K=576.
// Fused single kernel, TWO independent 256-thread warp-groups per CTA,
// each with its own tile stream / f32 stage buf / fp16 buf / named barrier.
// Shared W fragments in smem. fp16 m16n8k16, warp 32o x 32t, T_TILE=128.

#define T_LEN   65536
#define NB      8
#define NO      64
#define NC      64
#define T_TILE  128
#define HALO    17
#define XROWS   162          // fp16 rows per tile
#define XPW     36           // fp16 row stride in words (144B; LDS bank-clean)
#define FS      168          // f32 row stride in words (672B = 42 x 16B)
#define NCHUNK  36           // K=576/16
#define GRID    148
#define NGRP    296          // GRID * 2
#define NTILES  4096         // NB * T_LEN/T_TILE

// smem byte offsets
#define WFOFF   0
#define WFBYTES (NCHUNK*4*32*16)         // 73728
#define GF(g)   (WFBYTES + (g)*66336)            // f32 buf: 64*672 = 43008
#define GX(g)   (WFBYTES + (g)*66336 + 43008)    // fp16 buf: 162*144 = 23328
#define SMTOT   (WFBYTES + 2*66336)      // 206400

extern __shared__ char sm[];

__device__ __forceinline__ uint32_t s2u(const void* p) {
    uint32_t a;
    asm("{ .reg .u64 t; cvta.to.shared.u64 t, %1; cvt.u32.u64 %0, t; }"
        : "=r"(a) : "l"(p));
    return a;
}
__device__ __forceinline__ uint32_t packh2(float lo, float hi) {
    __half2 h = __floats2half2_rn(lo, hi);
    return *(uint32_t*)&h;
}

#define CP_ASYNC16(d, s) \
    asm volatile("cp.async.cg.shared.global [%0], [%1], 16;" :: "r"(d), "l"(s))
#define CP_COMMIT() asm volatile("cp.async.commit_group;" ::: "memory")
#define CP_WAIT0()  asm volatile("cp.async.wait_group 0;" ::: "memory")
#define BAR_G(id)   asm volatile("bar.sync %0, 256;" :: "r"(id) : "memory")

// Stage one tile's raw f32 rows [c][t0-20 .. t0+148) into this group's buffer.
__device__ __forceinline__ void stage_f32(const float* __restrict__ x,
                                          int tile, uint32_t fbase, int tidg) {
    const int b  = tile >> 9;
    const int t0 = (tile & 511) << 7;
    const int ts0 = t0 - 20;
    const float* xb = x + (size_t)(b * 64) * T_LEN;
#pragma unroll
    for (int s = 0; s < 11; ++s) {
        int idx = s * 256 + tidg;
        if (idx < 64 * 42) {
            int r = idx / 42, k = idx - r * 42;
            int ts = ts0 + 4 * k;
            uint32_t doff = fbase + (uint32_t)(r * FS + 4 * k) * 4;
            if (ts >= 0 && ts < T_LEN)
                CP_ASYNC16(doff, xb + (size_t)r * T_LEN + ts);
            else
                *(uint4*)(sm + (doff - s2u(sm))) = make_uint4(0, 0, 0, 0);
        }
    }
}

__global__ __launch_bounds__(512, 1) void taconv_mma(
    const float* __restrict__ x, const float* __restrict__ w,
    const float* __restrict__ bias, float* __restrict__ out)
{
    const int tid  = threadIdx.x;
    const int grp  = tid >> 8;           // warp-group 0 / 1
    const int tidg = tid & 255;
    const int widg = tidg >> 5;
    const int lane = tid & 31;
    const int og   = widg & 1;           // o-half: 2 mtiles of 16
    const int tg   = widg >> 1;          // t-group: 32 t each (4 groups)

    const uint32_t smb  = s2u(sm);
    const uint32_t fbase = smb + GF(grp);
    const uint32_t xbase = smb + GX(grp);

    // ---- first tile staging (both groups), then cook W frags (overlapped) ----
    int tile = blockIdx.x * 2 + grp;
    stage_f32(x, tile, fbase, tidg);
    CP_COMMIT();

    {   // W fragments: exact m16n8k16 f16 A-frag layout (shared by both groups)
        uint4* sw = (uint4*)(sm + WFOFF);
#pragma unroll
        for (int e = tid; e < NCHUNK * 128; e += 512) {
            int q = e >> 7, rr = e & 127, mt = rr >> 5, ln = rr & 31;
            int j = q >> 2, cq = q & 3;
            int o0 = mt * 16 + (ln >> 2);
            int c0 = cq * 16 + (ln & 3) * 2;
            uint4 u;
            u.x = packh2(w[o0*576 + c0*9 + j],        w[o0*576 + (c0+1)*9 + j]);
            u.y = packh2(w[(o0+8)*576 + c0*9 + j],    w[(o0+8)*576 + (c0+1)*9 + j]);
            u.z = packh2(w[o0*576 + (c0+8)*9 + j],    w[o0*576 + (c0+9)*9 + j]);
            u.w = packh2(w[(o0+8)*576 + (c0+8)*9 + j],w[(o0+8)*576 + (c0+9)*9 + j]);
            sw[e] = u;
        }
    }
    const int oA0 = og * 32 + (lane >> 2);
    float bv[2][2];
#pragma unroll
    for (int m = 0; m < 2; ++m) {
        bv[m][0] = __ldg(bias + oA0 + m * 16);
        bv[m][1] = __ldg(bias + oA0 + m * 16 + 8);
    }
    __syncthreads();     // W visible to both groups; groups now independent

    const int wrow = tg * 32 + (lane >> 2);   // B-frag t-row base (pre-shift)
    const int barid = grp + 1;

    for (; tile < NTILES; tile += NGRP) {
        CP_WAIT0();
        BAR_G(barid);        // f32 visible group-wide; prev compute done

        // ---- convert f32 [c][i+3] -> fp16 [i][c] for this group's tile ----
        {
            const float* fb = (const float*)(sm + GF(grp));
#pragma unroll
            for (int u = tidg; u < 8 * XROWS; u += 256) {
                int wblk = u / XROWS, i = u - wblk * XROWS;
                const float* src = fb + (8 * wblk) * FS + i + 3;
                uint32_t h0 = packh2(src[0],      src[FS]);
                uint32_t h1 = packh2(src[2*FS],   src[3*FS]);
                uint32_t h2 = packh2(src[4*FS],   src[5*FS]);
                uint32_t h3 = packh2(src[6*FS],   src[7*FS]);
                *(uint4*)(sm + GX(grp) + i * (XPW*4) + wblk * 16) =
                    make_uint4(h0, h1, h2, h3);
            }
        }
        BAR_G(barid);        // fp16 ready; f32 buffer free

        // ---- prefetch this group's next tile (overlaps compute) ----
        if (tile + NGRP < NTILES)
            stage_f32(x, tile + NGRP, fbase, tidg);
        CP_COMMIT();

        // ---- mainloop: 36 K-chunks, 8 mma each ----
        const uint32_t* xs = (const uint32_t*)(sm + GX(grp));
        const uint4* wf_base = (const uint4*)(sm + WFOFF);

        float acc[2][4][4];
#pragma unroll
        for (int m = 0; m < 2; ++m)
#pragma unroll
            for (int n = 0; n < 4; ++n) {
                acc[m][n][0] = bv[m][0]; acc[m][n][1] = bv[m][0];
                acc[m][n][2] = bv[m][1]; acc[m][n][3] = bv[m][1];
            }

#pragma unroll
        for (int j = 0; j < 9; ++j) {
            const int offj = 16 * (j / 3) + (j % 3);
#pragma unroll
            for (int cq = 0; cq < 4; ++cq) {
                const int q = j * 4 + cq;
                uint4 wf[2];
#pragma unroll
                for (int m = 0; m < 2; ++m)
                    wf[m] = wf_base[(q * 4 + og * 2 + m) * 32 + lane];

                uint32_t bb[4][2];
                const uint32_t* bp =
                    xs + (wrow + offj) * XPW + cq * 8 + (lane & 3);
#pragma unroll
                for (int nt = 0; nt < 4; ++nt) {
                    bb[nt][0] = bp[nt * 8 * XPW];
                    bb[nt][1] = bp[nt * 8 * XPW + 4];
                }
#pragma unroll
                for (int m = 0; m < 2; ++m)
#pragma unroll
                    for (int nt = 0; nt < 4; ++nt)
                        asm volatile(
                            "mma.sync.aligned.m16n8k16.row.col.f32.f16.f16.f32 "
                            "{%0,%1,%2,%3}, {%4,%5,%6,%7}, {%8,%9}, {%0,%1,%2,%3};"
                            : "+f"(acc[m][nt][0]), "+f"(acc[m][nt][1]),
                              "+f"(acc[m][nt][2]), "+f"(acc[m][nt][3])
                            : "r"(wf[m].x), "r"(wf[m].y),
                              "r"(wf[m].z), "r"(wf[m].w),
                              "r"(bb[nt][0]), "r"(bb[nt][1]));
            }
        }

        // ---- epilogue: pure stores (bias already in acc) ----
        const int b  = tile >> 9;
        const int t0 = (tile & 511) << 7;
        float* ob = out + (size_t)b * NO * T_LEN + t0 + tg * 32 + 2 * (lane & 3);
#pragma unroll
        for (int m = 0; m < 2; ++m) {
            int oA = oA0 + m * 16;
#pragma unroll
            for (int nt = 0; nt < 4; ++nt) {
                *(float2*)(ob + (size_t)oA * T_LEN + nt * 8) =
                    make_float2(acc[m][nt][0], acc[m][nt][1]);
                *(float2*)(ob + (size_t)(oA + 8) * T_LEN + nt * 8) =
                    make_float2(acc[m][nt][2], acc[m][nt][3]);
            }
        }
    }
}

extern "C" void kernel_launch(void* const* d_in, const int* in_sizes, int n_in,
                              void* d_out, int out_size) {
    const float* x    = (const float*)d_in[0];
    const float* w    = (const float*)d_in[1];
    const float* bias = (const float*)d_in[2];
    float* out = (float*)d_out;

    cudaFuncSetAttribute(taconv_mma,
                         cudaFuncAttributeMaxDynamicSharedMemorySize, SMTOT);
    taconv_mma<<<GRID, 512, SMTOT>>>(x, w, bias, out);
}